// round 1
// baseline (speedup 1.0000x reference)
#include <cuda_runtime.h>
#include <cuda_bf16.h>
#include <math.h>

#define S_LEN   4096
#define DMODEL  768
#define NHEADS  12
#define DHEAD   64

// ---------------- scratch (no allocations allowed) ----------------
__device__ float g_qh[NHEADS * S_LEN * DHEAD];   // [h][s][d]
__device__ float g_kh[NHEADS * S_LEN * DHEAD];
__device__ float g_vh[NHEADS * S_LEN * DHEAD];
__device__ float g_att[S_LEN * DMODEL];          // [s][h*64+d]

// =================================================================
// SGEMM: C[M,N] = A[M,K] * W[N,K]^T + bias,  M=4096, N=K=768
// 128x128 block tile, BK=16, 8x8 per thread, 256 threads.
// HEAD_OUT: store into per-head layout [h][s][d] (h = n/64, d = n%64)
// =================================================================
template<bool HEAD_OUT>
__global__ __launch_bounds__(256)
void gemm_bias_kernel(const float* __restrict__ A,
                      const float* __restrict__ W,
                      const float* __restrict__ bias,
                      float* __restrict__ C)
{
    __shared__ float As[16][132];   // [k][m], padded
    __shared__ float Bs[16][132];   // [k][n], padded

    const int tid = threadIdx.x;
    const int tx  = tid & 15;       // 0..15 -> n
    const int ty  = tid >> 4;       // 0..15 -> m
    const int m0  = blockIdx.y * 128;
    const int n0  = blockIdx.x * 128;

    const int lr = tid >> 2;        // 0..63
    const int lc = (tid & 3) << 2;  // 0,4,8,12

    float acc[8][8];
#pragma unroll
    for (int i = 0; i < 8; ++i)
#pragma unroll
        for (int j = 0; j < 8; ++j) acc[i][j] = 0.f;

    for (int k0 = 0; k0 < DMODEL; k0 += 16) {
#pragma unroll
        for (int hh = 0; hh < 2; ++hh) {
            const int r = lr + hh * 64;
            float4 a = *(const float4*)(A + (size_t)(m0 + r) * DMODEL + k0 + lc);
            As[lc + 0][r] = a.x; As[lc + 1][r] = a.y;
            As[lc + 2][r] = a.z; As[lc + 3][r] = a.w;
            float4 b = *(const float4*)(W + (size_t)(n0 + r) * DMODEL + k0 + lc);
            Bs[lc + 0][r] = b.x; Bs[lc + 1][r] = b.y;
            Bs[lc + 2][r] = b.z; Bs[lc + 3][r] = b.w;
        }
        __syncthreads();

#pragma unroll
        for (int kk = 0; kk < 16; ++kk) {
            float ar[8], br[8];
            *(float4*)(ar)     = *(const float4*)&As[kk][ty * 8];
            *(float4*)(ar + 4) = *(const float4*)&As[kk][ty * 8 + 4];
            *(float4*)(br)     = *(const float4*)&Bs[kk][tx * 8];
            *(float4*)(br + 4) = *(const float4*)&Bs[kk][tx * 8 + 4];
#pragma unroll
            for (int i = 0; i < 8; ++i)
#pragma unroll
                for (int j = 0; j < 8; ++j)
                    acc[i][j] += ar[i] * br[j];
        }
        __syncthreads();
    }

#pragma unroll
    for (int i = 0; i < 8; ++i) {
        const int m = m0 + ty * 8 + i;
#pragma unroll
        for (int j = 0; j < 8; ++j) {
            const int n = n0 + tx * 8 + j;
            const float v = acc[i][j] + bias[n];
            if (HEAD_OUT) {
                C[(size_t)(n >> 6) * (S_LEN * DHEAD) + (size_t)m * DHEAD + (n & 63)];
                C[(size_t)(n >> 6) * (S_LEN * DHEAD) + (size_t)m * DHEAD + (n & 63)] = v;
            } else {
                C[(size_t)m * DMODEL + n] = v;
            }
        }
    }
}

// =================================================================
// Flash attention (causal), fp32, per-head. BR=BC=64, d=64.
// 256 threads: 16x16 grid, 4x4 register tiles for QK^T and PV.
// grid = (S/64, NHEADS)
// =================================================================
#define FPAD 65
#define FLASH_SMEM (4 * 64 * FPAD * sizeof(float))

__global__ __launch_bounds__(256)
void flash_kernel(const float* __restrict__ Q,   // [h][s][64]
                  const float* __restrict__ K,
                  const float* __restrict__ V,
                  float* __restrict__ O)         // [s][768]
{
    extern __shared__ float sm[];
    float* Qs = sm;
    float* Ks = sm + 64 * FPAD;
    float* Vs = sm + 2 * 64 * FPAD;
    float* Ps = sm + 3 * 64 * FPAD;

    const int tid = threadIdx.x;
    const int tx  = tid & 15;       // key/d-col group
    const int ty  = tid >> 4;       // row group
    const int qt  = blockIdx.x;
    const int h   = blockIdx.y;
    const int m0  = qt * 64;

    const float* Qh = Q + (size_t)h * S_LEN * DHEAD;
    const float* Kh = K + (size_t)h * S_LEN * DHEAD;
    const float* Vh = V + (size_t)h * S_LEN * DHEAD;

    // load Q tile (64x64)
    {
        const int r  = tid >> 2;
        const int c0 = (tid & 3) << 4;
#pragma unroll
        for (int u = 0; u < 4; ++u) {
            float4 t = *(const float4*)(Qh + (size_t)(m0 + r) * DHEAD + c0 + u * 4);
            Qs[r * FPAD + c0 + u * 4 + 0] = t.x;
            Qs[r * FPAD + c0 + u * 4 + 1] = t.y;
            Qs[r * FPAD + c0 + u * 4 + 2] = t.z;
            Qs[r * FPAD + c0 + u * 4 + 3] = t.w;
        }
    }

    float o[4][4];
    float mrow[4], lrow[4];
#pragma unroll
    for (int i = 0; i < 4; ++i) {
        mrow[i] = -1e30f; lrow[i] = 0.f;
#pragma unroll
        for (int j = 0; j < 4; ++j) o[i][j] = 0.f;
    }

    const int nT = qt + 1;   // causal: key tiles 0..qt
    for (int jt = 0; jt < nT; ++jt) {
        const int j0 = jt * 64;
        __syncthreads();    // prior-tile readers done before overwrite
        {
            const int r  = tid >> 2;
            const int c0 = (tid & 3) << 4;
#pragma unroll
            for (int u = 0; u < 4; ++u) {
                float4 kt = *(const float4*)(Kh + (size_t)(j0 + r) * DHEAD + c0 + u * 4);
                Ks[r * FPAD + c0 + u * 4 + 0] = kt.x;
                Ks[r * FPAD + c0 + u * 4 + 1] = kt.y;
                Ks[r * FPAD + c0 + u * 4 + 2] = kt.z;
                Ks[r * FPAD + c0 + u * 4 + 3] = kt.w;
                float4 vt = *(const float4*)(Vh + (size_t)(j0 + r) * DHEAD + c0 + u * 4);
                Vs[r * FPAD + c0 + u * 4 + 0] = vt.x;
                Vs[r * FPAD + c0 + u * 4 + 1] = vt.y;
                Vs[r * FPAD + c0 + u * 4 + 2] = vt.z;
                Vs[r * FPAD + c0 + u * 4 + 3] = vt.w;
            }
        }
        __syncthreads();

        // ---- scores: S = Q Kt  (4x4 per thread) ----
        float s[4][4];
#pragma unroll
        for (int i = 0; i < 4; ++i)
#pragma unroll
            for (int j = 0; j < 4; ++j) s[i][j] = 0.f;

#pragma unroll 8
        for (int d = 0; d < 64; ++d) {
            float ar[4], br[4];
#pragma unroll
            for (int i = 0; i < 4; ++i) ar[i] = Qs[(ty * 4 + i) * FPAD + d];
#pragma unroll
            for (int j = 0; j < 4; ++j) br[j] = Ks[(tx * 4 + j) * FPAD + d];
#pragma unroll
            for (int i = 0; i < 4; ++i)
#pragma unroll
                for (int j = 0; j < 4; ++j)
                    s[i][j] += ar[i] * br[j];
        }

        // scale + causal mask
#pragma unroll
        for (int i = 0; i < 4; ++i) {
            const int qi = m0 + ty * 4 + i;
#pragma unroll
            for (int j = 0; j < 4; ++j) {
                const int kj = j0 + tx * 4 + j;
                s[i][j] = (kj <= qi) ? s[i][j] * 0.125f : -1e30f;
            }
        }

        // ---- online softmax (row reduced across 16 tx lanes) ----
#pragma unroll
        for (int i = 0; i < 4; ++i) {
            float tmax = fmaxf(fmaxf(s[i][0], s[i][1]), fmaxf(s[i][2], s[i][3]));
#pragma unroll
            for (int off = 8; off > 0; off >>= 1)
                tmax = fmaxf(tmax, __shfl_xor_sync(0xffffffffu, tmax, off, 16));
            const float mnew  = fmaxf(mrow[i], tmax);
            const float alpha = __expf(mrow[i] - mnew);
            float p[4];
            float lsum = 0.f;
#pragma unroll
            for (int j = 0; j < 4; ++j) { p[j] = __expf(s[i][j] - mnew); lsum += p[j]; }
#pragma unroll
            for (int off = 8; off > 0; off >>= 1)
                lsum += __shfl_xor_sync(0xffffffffu, lsum, off, 16);
            lrow[i] = lrow[i] * alpha + lsum;
            mrow[i] = mnew;
#pragma unroll
            for (int j = 0; j < 4; ++j) o[i][j] *= alpha;
#pragma unroll
            for (int j = 0; j < 4; ++j)
                Ps[(ty * 4 + i) * FPAD + tx * 4 + j] = p[j];
        }
        __syncthreads();

        // ---- O += P V  (4x4 per thread; thread's cols = d dims) ----
#pragma unroll 8
        for (int kk = 0; kk < 64; ++kk) {
            float pr[4], vr[4];
#pragma unroll
            for (int i = 0; i < 4; ++i) pr[i] = Ps[(ty * 4 + i) * FPAD + kk];
#pragma unroll
            for (int j = 0; j < 4; ++j) vr[j] = Vs[kk * FPAD + tx * 4 + j];
#pragma unroll
            for (int i = 0; i < 4; ++i)
#pragma unroll
                for (int j = 0; j < 4; ++j)
                    o[i][j] += pr[i] * vr[j];
        }
    }

    // epilogue: normalize + write [s][h*64 + d]
#pragma unroll
    for (int i = 0; i < 4; ++i) {
        const float inv = 1.f / lrow[i];
        const int m = m0 + ty * 4 + i;
#pragma unroll
        for (int j = 0; j < 4; ++j)
            O[(size_t)m * DMODEL + h * DHEAD + tx * 4 + j] = o[i][j] * inv;
    }
}

// =================================================================
extern "C" void kernel_launch(void* const* d_in, const int* in_sizes, int n_in,
                              void* d_out, int out_size)
{
    const float* q  = (const float*)d_in[0];
    const float* k  = (const float*)d_in[1];
    const float* v  = (const float*)d_in[2];
    const float* wq = (const float*)d_in[3];
    const float* bq = (const float*)d_in[4];
    const float* wk = (const float*)d_in[5];
    const float* bk = (const float*)d_in[6];
    const float* wv = (const float*)d_in[7];
    const float* bv = (const float*)d_in[8];
    const float* wo = (const float*)d_in[9];
    const float* bo = (const float*)d_in[10];
    float* out = (float*)d_out;

    void *pq, *pk, *pv, *patt;
    cudaGetSymbolAddress(&pq,   g_qh);
    cudaGetSymbolAddress(&pk,   g_kh);
    cudaGetSymbolAddress(&pv,   g_vh);
    cudaGetSymbolAddress(&patt, g_att);
    float* gq   = (float*)pq;
    float* gk   = (float*)pk;
    float* gv   = (float*)pv;
    float* gatt = (float*)patt;

    const dim3 ggrid(DMODEL / 128, S_LEN / 128);   // (6, 32)

    gemm_bias_kernel<true><<<ggrid, 256>>>(q, wq, bq, gq);
    gemm_bias_kernel<true><<<ggrid, 256>>>(k, wk, bk, gk);
    gemm_bias_kernel<true><<<ggrid, 256>>>(v, wv, bv, gv);

    cudaFuncSetAttribute(flash_kernel,
                         cudaFuncAttributeMaxDynamicSharedMemorySize,
                         (int)FLASH_SMEM);
    flash_kernel<<<dim3(S_LEN / 64, NHEADS), 256, FLASH_SMEM>>>(gq, gk, gv, gatt);

    gemm_bias_kernel<false><<<ggrid, 256>>>(gatt, wo, bo, out);
}

// round 2
// speedup vs baseline: 2.6867x; 2.6867x over previous
#include <cuda_runtime.h>
#include <cuda_bf16.h>
#include <math.h>

#define S_LEN   4096
#define DMODEL  768
#define NHEADS  12
#define DHEAD   64

// ---------------- scratch (no allocations allowed) ----------------
__device__ float g_qh[NHEADS * S_LEN * DHEAD];   // [h][s][d]
__device__ float g_kh[NHEADS * S_LEN * DHEAD];
__device__ float g_vh[NHEADS * S_LEN * DHEAD];
__device__ float g_att[S_LEN * DMODEL];          // [s][h*64+d]

// ---------------- tf32 helpers ----------------
__device__ __forceinline__ unsigned f2tf32(float x) {
    unsigned r;
    asm("cvt.rna.tf32.f32 %0, %1;" : "=r"(r) : "f"(x));
    return r;
}

// D += A(16x8) * B(8x8), tf32 inputs, fp32 accum.
// A frag: a0=(r,c) a1=(r+8,c) a2=(r,c+4) a3=(r+8,c+4), r=lane/4, c=lane%4
// B frag: b0=(k=c, n=r)  b1=(k=c+4, n=r)
// C frag: c0=(r,2c) c1=(r,2c+1) c2=(r+8,2c) c3=(r+8,2c+1)
__device__ __forceinline__ void mma_tf32(float* c, unsigned a0, unsigned a1,
                                         unsigned a2, unsigned a3,
                                         unsigned b0, unsigned b1) {
    asm("mma.sync.aligned.m16n8k8.row.col.f32.tf32.tf32.f32 "
        "{%0,%1,%2,%3}, {%4,%5,%6,%7}, {%8,%9}, {%0,%1,%2,%3};"
        : "+f"(c[0]), "+f"(c[1]), "+f"(c[2]), "+f"(c[3])
        : "r"(a0), "r"(a1), "r"(a2), "r"(a3), "r"(b0), "r"(b1));
}

// =================================================================
// tf32 GEMM: C[M,N] = A[M,K] * W[N,K]^T + bias. M=4096, N=K=768.
// 128x128 block tile, BK=32, 256 thr (8 warps, 2x4 m x n), warp=64x32.
// smem stride 36 -> fragment loads & stores conflict-free.
// =================================================================
#define GSTR 36

template<bool HEAD_OUT>
__global__ __launch_bounds__(256)
void gemm_tf32_kernel(const float* __restrict__ A,
                      const float* __restrict__ W,
                      const float* __restrict__ bias,
                      float* __restrict__ C)
{
    __shared__ unsigned As[128 * GSTR];
    __shared__ unsigned Ws[128 * GSTR];

    const int tid  = threadIdx.x;
    const int warp = tid >> 5;
    const int lane = tid & 31;
    const int gid  = lane >> 2;   // groupID
    const int tig  = lane & 3;    // threadID_in_group

    const int m0 = blockIdx.y * 128;
    const int n0 = blockIdx.x * 128;
    const int wm = (warp >> 2) * 64;   // 0 or 64
    const int wn = (warp & 3) * 32;    // 0..96

    float acc[4][4][4];                 // [mi][ni][frag]
#pragma unroll
    for (int mi = 0; mi < 4; ++mi)
#pragma unroll
        for (int ni = 0; ni < 4; ++ni)
#pragma unroll
            for (int f = 0; f < 4; ++f) acc[mi][ni][f] = 0.f;

    for (int k0 = 0; k0 < DMODEL; k0 += 32) {
        __syncthreads();
        // each warp loads 16 rows of each tile; lane = k column
#pragma unroll
        for (int i = 0; i < 16; ++i) {
            const int r = warp * 16 + i;
            As[r * GSTR + lane] = f2tf32(A[(size_t)(m0 + r) * DMODEL + k0 + lane]);
            Ws[r * GSTR + lane] = f2tf32(W[(size_t)(n0 + r) * DMODEL + k0 + lane]);
        }
        __syncthreads();

#pragma unroll
        for (int kk = 0; kk < 4; ++kk) {
            const int k4 = kk * 8;
            unsigned a[4][4], b[4][2];
#pragma unroll
            for (int mi = 0; mi < 4; ++mi) {
                const int r = wm + mi * 16 + gid;
                a[mi][0] = As[r * GSTR + k4 + tig];
                a[mi][1] = As[(r + 8) * GSTR + k4 + tig];
                a[mi][2] = As[r * GSTR + k4 + tig + 4];
                a[mi][3] = As[(r + 8) * GSTR + k4 + tig + 4];
            }
#pragma unroll
            for (int ni = 0; ni < 4; ++ni) {
                const int n = wn + ni * 8 + gid;
                b[ni][0] = Ws[n * GSTR + k4 + tig];
                b[ni][1] = Ws[n * GSTR + k4 + tig + 4];
            }
#pragma unroll
            for (int mi = 0; mi < 4; ++mi)
#pragma unroll
                for (int ni = 0; ni < 4; ++ni)
                    mma_tf32(acc[mi][ni], a[mi][0], a[mi][1], a[mi][2], a[mi][3],
                             b[ni][0], b[ni][1]);
        }
    }

    // epilogue
#pragma unroll
    for (int mi = 0; mi < 4; ++mi) {
#pragma unroll
        for (int ni = 0; ni < 4; ++ni) {
            const int n = n0 + wn + ni * 8 + 2 * tig;
            const float b0 = bias[n], b1 = bias[n + 1];
#pragma unroll
            for (int half = 0; half < 2; ++half) {
                const int m = m0 + wm + mi * 16 + gid + half * 8;
                const float v0 = acc[mi][ni][half * 2 + 0] + b0;
                const float v1 = acc[mi][ni][half * 2 + 1] + b1;
                if (HEAD_OUT) {
                    float* dst = C + (size_t)(n >> 6) * (S_LEN * DHEAD)
                                   + (size_t)m * DHEAD + (n & 63);
                    dst[0] = v0; dst[1] = v1;
                } else {
                    float* dst = C + (size_t)m * DMODEL + n;
                    dst[0] = v0; dst[1] = v1;
                }
            }
        }
    }
}

// =================================================================
// Flash attention (causal), tf32 mma. BR=128, BC=64, d=64.
// 256 thr, 8 warps; warp w owns query rows [w*16, w*16+16).
// grid = (S/128, NHEADS)
// =================================================================
#define FSTR 68
#define FLASH_SMEM ((128 + 64 + 64 + 128) * FSTR * 4)

__global__ __launch_bounds__(256)
void flash_tf32_kernel(const float* __restrict__ Q,   // [h][s][64]
                       const float* __restrict__ K,
                       const float* __restrict__ V,
                       float* __restrict__ O)          // [s][768]
{
    extern __shared__ unsigned fsm[];
    unsigned* Qs = fsm;                       // 128 x FSTR
    unsigned* Ks = Qs + 128 * FSTR;           // 64 x FSTR
    unsigned* Vs = Ks + 64 * FSTR;            // 64 x FSTR
    unsigned* Ps = Vs + 64 * FSTR;            // 128 x FSTR

    const int tid  = threadIdx.x;
    const int warp = tid >> 5;
    const int lane = tid & 31;
    const int gid  = lane >> 2;
    const int tig  = lane & 3;

    const int bx = blockIdx.x;
    const int h  = blockIdx.y;
    const int m0 = bx * 128;
    const int w16 = warp * 16;

    const float* Qh = Q + (size_t)h * S_LEN * DHEAD;
    const float* Kh = K + (size_t)h * S_LEN * DHEAD;
    const float* Vh = V + (size_t)h * S_LEN * DHEAD;

    // load Q tile (128x64), tf32-convert at store
#pragma unroll
    for (int i = 0; i < 16; ++i) {
        const int r = w16 + i;
        Qs[r * FSTR + lane]      = f2tf32(Qh[(size_t)(m0 + r) * DHEAD + lane]);
        Qs[r * FSTR + lane + 32] = f2tf32(Qh[(size_t)(m0 + r) * DHEAD + lane + 32]);
    }

    float o[8][4];
#pragma unroll
    for (int ni = 0; ni < 8; ++ni)
#pragma unroll
        for (int f = 0; f < 4; ++f) o[ni][f] = 0.f;
    float mrun0 = -1e30f, mrun1 = -1e30f;
    float lrun0 = 0.f,    lrun1 = 0.f;

    const int nT = 2 * (bx + 1);
    for (int jt = 0; jt < nT; ++jt) {
        const int j0 = jt * 64;
        const bool masked = (jt >= 2 * bx);

        __syncthreads();   // previous-iter readers of Ks/Vs done
#pragma unroll
        for (int i = 0; i < 8; ++i) {
            const int r = warp * 8 + i;
            Ks[r * FSTR + lane]      = f2tf32(Kh[(size_t)(j0 + r) * DHEAD + lane]);
            Ks[r * FSTR + lane + 32] = f2tf32(Kh[(size_t)(j0 + r) * DHEAD + lane + 32]);
            Vs[r * FSTR + lane]      = f2tf32(Vh[(size_t)(j0 + r) * DHEAD + lane]);
            Vs[r * FSTR + lane + 32] = f2tf32(Vh[(size_t)(j0 + r) * DHEAD + lane + 32]);
        }
        __syncthreads();

        // ---- S = Q K^T (m16 x n64, k=64) ----
        float s[8][4];
#pragma unroll
        for (int ni = 0; ni < 8; ++ni)
#pragma unroll
            for (int f = 0; f < 4; ++f) s[ni][f] = 0.f;

#pragma unroll
        for (int kk = 0; kk < 8; ++kk) {
            const int k8 = kk * 8;
            const int r = w16 + gid;
            unsigned a0 = Qs[r * FSTR + k8 + tig];
            unsigned a1 = Qs[(r + 8) * FSTR + k8 + tig];
            unsigned a2 = Qs[r * FSTR + k8 + tig + 4];
            unsigned a3 = Qs[(r + 8) * FSTR + k8 + tig + 4];
#pragma unroll
            for (int ni = 0; ni < 8; ++ni) {
                const int n = ni * 8 + gid;
                unsigned b0 = Ks[n * FSTR + k8 + tig];
                unsigned b1 = Ks[n * FSTR + k8 + tig + 4];
                mma_tf32(s[ni], a0, a1, a2, a3, b0, b1);
            }
        }

        // ---- scale + causal mask ----
        if (masked) {
            const int q0 = m0 + w16 + gid;      // row of c0/c1
            const int q1 = q0 + 8;              // row of c2/c3
#pragma unroll
            for (int ni = 0; ni < 8; ++ni) {
                const int kc0 = j0 + ni * 8 + 2 * tig;
                const int kc1 = kc0 + 1;
                s[ni][0] = (kc0 <= q0) ? s[ni][0] * 0.125f : -1e30f;
                s[ni][1] = (kc1 <= q0) ? s[ni][1] * 0.125f : -1e30f;
                s[ni][2] = (kc0 <= q1) ? s[ni][2] * 0.125f : -1e30f;
                s[ni][3] = (kc1 <= q1) ? s[ni][3] * 0.125f : -1e30f;
            }
        } else {
#pragma unroll
            for (int ni = 0; ni < 8; ++ni)
#pragma unroll
                for (int f = 0; f < 4; ++f) s[ni][f] *= 0.125f;
        }

        // ---- online softmax: rows (w16+gid) and (w16+gid+8) ----
        float mx0 = -1e30f, mx1 = -1e30f;
#pragma unroll
        for (int ni = 0; ni < 8; ++ni) {
            mx0 = fmaxf(mx0, fmaxf(s[ni][0], s[ni][1]));
            mx1 = fmaxf(mx1, fmaxf(s[ni][2], s[ni][3]));
        }
#pragma unroll
        for (int off = 1; off <= 2; off <<= 1) {
            mx0 = fmaxf(mx0, __shfl_xor_sync(0xffffffffu, mx0, off));
            mx1 = fmaxf(mx1, __shfl_xor_sync(0xffffffffu, mx1, off));
        }
        const float mnew0 = fmaxf(mrun0, mx0);
        const float mnew1 = fmaxf(mrun1, mx1);
        const float al0 = __expf(mrun0 - mnew0);
        const float al1 = __expf(mrun1 - mnew1);
        mrun0 = mnew0; mrun1 = mnew1;

        float ls0 = 0.f, ls1 = 0.f;
#pragma unroll
        for (int ni = 0; ni < 8; ++ni) {
            const float p0 = __expf(s[ni][0] - mnew0);
            const float p1 = __expf(s[ni][1] - mnew0);
            const float p2 = __expf(s[ni][2] - mnew1);
            const float p3 = __expf(s[ni][3] - mnew1);
            ls0 += p0 + p1; ls1 += p2 + p3;
            const int r0 = w16 + gid;
            const int c  = ni * 8 + 2 * tig;
            Ps[r0 * FSTR + c]           = f2tf32(p0);
            Ps[r0 * FSTR + c + 1]       = f2tf32(p1);
            Ps[(r0 + 8) * FSTR + c]     = f2tf32(p2);
            Ps[(r0 + 8) * FSTR + c + 1] = f2tf32(p3);
        }
#pragma unroll
        for (int off = 1; off <= 2; off <<= 1) {
            ls0 += __shfl_xor_sync(0xffffffffu, ls0, off);
            ls1 += __shfl_xor_sync(0xffffffffu, ls1, off);
        }
        lrun0 = lrun0 * al0 + ls0;
        lrun1 = lrun1 * al1 + ls1;

#pragma unroll
        for (int ni = 0; ni < 8; ++ni) {
            o[ni][0] *= al0; o[ni][1] *= al0;
            o[ni][2] *= al1; o[ni][3] *= al1;
        }

        __syncwarp();   // Ps is warp-private: lanes exchange via smem

        // ---- O += P V (m16 x n64(d), k=64(keys)) ----
#pragma unroll
        for (int kk = 0; kk < 8; ++kk) {
            const int k8 = kk * 8;
            const int r = w16 + gid;
            unsigned a0 = Ps[r * FSTR + k8 + tig];
            unsigned a1 = Ps[(r + 8) * FSTR + k8 + tig];
            unsigned a2 = Ps[r * FSTR + k8 + tig + 4];
            unsigned a3 = Ps[(r + 8) * FSTR + k8 + tig + 4];
#pragma unroll
            for (int ni = 0; ni < 8; ++ni) {
                const int n = ni * 8 + gid;
                unsigned b0 = Vs[(k8 + tig) * FSTR + n];
                unsigned b1 = Vs[(k8 + tig + 4) * FSTR + n];
                mma_tf32(o[ni], a0, a1, a2, a3, b0, b1);
            }
        }
        __syncwarp();   // done reading Ps before next-iter overwrite
    }

    // epilogue: normalize + write [s][h*64 + d]
    const float inv0 = 1.f / lrun0;
    const float inv1 = 1.f / lrun1;
    const int r0 = m0 + w16 + gid;
#pragma unroll
    for (int ni = 0; ni < 8; ++ni) {
        const int c = h * DHEAD + ni * 8 + 2 * tig;
        float* d0 = O + (size_t)r0 * DMODEL + c;
        float* d1 = O + (size_t)(r0 + 8) * DMODEL + c;
        d0[0] = o[ni][0] * inv0; d0[1] = o[ni][1] * inv0;
        d1[0] = o[ni][2] * inv1; d1[1] = o[ni][3] * inv1;
    }
}

// =================================================================
extern "C" void kernel_launch(void* const* d_in, const int* in_sizes, int n_in,
                              void* d_out, int out_size)
{
    const float* q  = (const float*)d_in[0];
    const float* k  = (const float*)d_in[1];
    const float* v  = (const float*)d_in[2];
    const float* wq = (const float*)d_in[3];
    const float* bq = (const float*)d_in[4];
    const float* wk = (const float*)d_in[5];
    const float* bk = (const float*)d_in[6];
    const float* wv = (const float*)d_in[7];
    const float* bv = (const float*)d_in[8];
    const float* wo = (const float*)d_in[9];
    const float* bo = (const float*)d_in[10];
    float* out = (float*)d_out;

    void *pq, *pk, *pv, *patt;
    cudaGetSymbolAddress(&pq,   g_qh);
    cudaGetSymbolAddress(&pk,   g_kh);
    cudaGetSymbolAddress(&pv,   g_vh);
    cudaGetSymbolAddress(&patt, g_att);
    float* gq   = (float*)pq;
    float* gk   = (float*)pk;
    float* gv   = (float*)pv;
    float* gatt = (float*)patt;

    const dim3 ggrid(DMODEL / 128, S_LEN / 128);   // (6, 32)

    gemm_tf32_kernel<true><<<ggrid, 256>>>(q, wq, bq, gq);
    gemm_tf32_kernel<true><<<ggrid, 256>>>(k, wk, bk, gk);
    gemm_tf32_kernel<true><<<ggrid, 256>>>(v, wv, bv, gv);

    cudaFuncSetAttribute(flash_tf32_kernel,
                         cudaFuncAttributeMaxDynamicSharedMemorySize,
                         (int)FLASH_SMEM);
    flash_tf32_kernel<<<dim3(S_LEN / 128, NHEADS), 256, FLASH_SMEM>>>(gq, gk, gv, gatt);

    gemm_tf32_kernel<false><<<ggrid, 256>>>(gatt, wo, bo, out);
}

// round 3
// speedup vs baseline: 3.7519x; 1.3964x over previous
#include <cuda_runtime.h>
#include <cuda_bf16.h>
#include <math.h>

#define S_LEN   4096
#define DMODEL  768
#define NHEADS  12
#define DHEAD   64

// ---------------- scratch (no allocations allowed) ----------------
__device__ float g_qh[NHEADS * S_LEN * DHEAD];   // [h][s][d]
__device__ float g_kh[NHEADS * S_LEN * DHEAD];
__device__ float g_vh[NHEADS * S_LEN * DHEAD];
__device__ float g_att[S_LEN * DMODEL];          // [s][h*64+d]

// ---------------- helpers ----------------
__device__ __forceinline__ unsigned f2tf32(float x) {
    unsigned r;
    asm("cvt.rna.tf32.f32 %0, %1;" : "=r"(r) : "f"(x));
    return r;
}

__device__ __forceinline__ void cp_async16(void* smem, const void* g) {
    unsigned s = (unsigned)__cvta_generic_to_shared(smem);
    asm volatile("cp.async.cg.shared.global [%0], [%1], 16;" :: "r"(s), "l"(g));
}
__device__ __forceinline__ void cp_commit() {
    asm volatile("cp.async.commit_group;");
}
template<int N> __device__ __forceinline__ void cp_wait() {
    asm volatile("cp.async.wait_group %0;" :: "n"(N));
}

// D += A(16x8) * B(8x8), tf32 inputs, fp32 accum.
__device__ __forceinline__ void mma_tf32(float* c, unsigned a0, unsigned a1,
                                         unsigned a2, unsigned a3,
                                         unsigned b0, unsigned b1) {
    asm("mma.sync.aligned.m16n8k8.row.col.f32.tf32.tf32.f32 "
        "{%0,%1,%2,%3}, {%4,%5,%6,%7}, {%8,%9}, {%0,%1,%2,%3};"
        : "+f"(c[0]), "+f"(c[1]), "+f"(c[2]), "+f"(c[3])
        : "r"(a0), "r"(a1), "r"(a2), "r"(a3), "r"(b0), "r"(b1));
}

// =================================================================
// tf32 GEMM with cp.async 2-stage pipeline.
// C[M,N] = A[M,K]*W[N,K]^T + bias.  M=4096, N=K=768.
// 128x128 tile, BK=32, 256 thr, warp tile 64x32.
// blockIdx.z selects one of up to 3 (A,W,bias,C) tuples.
// =================================================================
#define GSTR 36
#define GEMM_STAGE (128 * GSTR)                  // words per matrix per stage
#define GEMM_SMEM  (2 * 2 * GEMM_STAGE * 4)      // 73728 bytes

struct GemmPtrs { const float* A; const float* W; const float* bias; float* C; };
struct GemmArgs3 { GemmPtrs p[3]; };

template<bool HEAD_OUT>
__global__ __launch_bounds__(256, 2)
void gemm_tf32_kernel(GemmArgs3 args)
{
    extern __shared__ float gsm[];
    const GemmPtrs gp = args.p[blockIdx.z];
    const float* __restrict__ A    = gp.A;
    const float* __restrict__ W    = gp.W;
    const float* __restrict__ bias = gp.bias;
    float* __restrict__ C          = gp.C;

    const int tid  = threadIdx.x;
    const int warp = tid >> 5;
    const int lane = tid & 31;
    const int gid  = lane >> 2;
    const int tig  = lane & 3;

    const int m0 = blockIdx.y * 128;
    const int n0 = blockIdx.x * 128;
    const int wm = (warp >> 2) * 64;
    const int wn = (warp & 3) * 32;

    // copy mapping: 1024 16B-chunks per matrix per stage
    const int cr  = tid >> 3;          // base row 0..31
    const int ccc = (tid & 7) << 2;    // col 0,4,..,28

    float acc[4][4][4];
#pragma unroll
    for (int mi = 0; mi < 4; ++mi)
#pragma unroll
        for (int ni = 0; ni < 4; ++ni)
#pragma unroll
            for (int f = 0; f < 4; ++f) acc[mi][ni][f] = 0.f;

    auto issue = [&](int kt, int st) {
        float* As = gsm + st * 2 * GEMM_STAGE;
        float* Ws = As + GEMM_STAGE;
        const int k0 = kt * 32;
#pragma unroll
        for (int i = 0; i < 4; ++i) {
            const int r = cr + i * 32;
            cp_async16(As + r * GSTR + ccc, A + (size_t)(m0 + r) * DMODEL + k0 + ccc);
            cp_async16(Ws + r * GSTR + ccc, W + (size_t)(n0 + r) * DMODEL + k0 + ccc);
        }
        cp_commit();
    };

    issue(0, 0);

    const int NKT = DMODEL / 32;   // 24
    for (int kt = 0; kt < NKT; ++kt) {
        const int buf = kt & 1;
        if (kt + 1 < NKT) { issue(kt + 1, buf ^ 1); cp_wait<1>(); }
        else              { cp_wait<0>(); }
        __syncthreads();

        const float* As = gsm + buf * 2 * GEMM_STAGE;
        const float* Ws = As + GEMM_STAGE;

#pragma unroll
        for (int kk = 0; kk < 4; ++kk) {
            const int k4 = kk * 8;
            unsigned a[4][4], b[4][2];
#pragma unroll
            for (int mi = 0; mi < 4; ++mi) {
                const int r = wm + mi * 16 + gid;
                a[mi][0] = f2tf32(As[r * GSTR + k4 + tig]);
                a[mi][1] = f2tf32(As[(r + 8) * GSTR + k4 + tig]);
                a[mi][2] = f2tf32(As[r * GSTR + k4 + tig + 4]);
                a[mi][3] = f2tf32(As[(r + 8) * GSTR + k4 + tig + 4]);
            }
#pragma unroll
            for (int ni = 0; ni < 4; ++ni) {
                const int n = wn + ni * 8 + gid;
                b[ni][0] = f2tf32(Ws[n * GSTR + k4 + tig]);
                b[ni][1] = f2tf32(Ws[n * GSTR + k4 + tig + 4]);
            }
#pragma unroll
            for (int mi = 0; mi < 4; ++mi)
#pragma unroll
                for (int ni = 0; ni < 4; ++ni)
                    mma_tf32(acc[mi][ni], a[mi][0], a[mi][1], a[mi][2], a[mi][3],
                             b[ni][0], b[ni][1]);
        }
        __syncthreads();
    }

    // epilogue
#pragma unroll
    for (int mi = 0; mi < 4; ++mi) {
#pragma unroll
        for (int ni = 0; ni < 4; ++ni) {
            const int n = n0 + wn + ni * 8 + 2 * tig;
            const float b0 = bias[n], b1 = bias[n + 1];
#pragma unroll
            for (int half = 0; half < 2; ++half) {
                const int m = m0 + wm + mi * 16 + gid + half * 8;
                const float v0 = acc[mi][ni][half * 2 + 0] + b0;
                const float v1 = acc[mi][ni][half * 2 + 1] + b1;
                if (HEAD_OUT) {
                    float* dst = C + (size_t)(n >> 6) * (S_LEN * DHEAD)
                                   + (size_t)m * DHEAD + (n & 63);
                    dst[0] = v0; dst[1] = v1;
                } else {
                    float* dst = C + (size_t)m * DMODEL + n;
                    dst[0] = v0; dst[1] = v1;
                }
            }
        }
    }
}

// =================================================================
// Flash attention (causal), tf32 mma, cp.async double-buffered K/V.
// BR=128, BC=64, d=64. 256 thr / 8 warps; warp w owns rows [16w,16w+16).
// Q fragments register-resident. grid=(32, 12), reversed bx for balance.
// =================================================================
#define FSTR 68
#define FL_KV_STAGE (64 * FSTR)                         // words per matrix
#define FLASH_SMEM ((4 * FL_KV_STAGE + 128 * FSTR) * 4) // 104448 bytes

__global__ __launch_bounds__(256, 2)
void flash_tf32_kernel(const float* __restrict__ Q,   // [h][s][64]
                       const float* __restrict__ K,
                       const float* __restrict__ V,
                       float* __restrict__ O)          // [s][768]
{
    extern __shared__ float fsm[];
    float* Kst = fsm;                       // 2 x 64 x FSTR
    float* Vst = fsm + 2 * FL_KV_STAGE;     // 2 x 64 x FSTR
    unsigned* Ps = (unsigned*)(fsm + 4 * FL_KV_STAGE);  // 128 x FSTR

    const int tid  = threadIdx.x;
    const int warp = tid >> 5;
    const int lane = tid & 31;
    const int gid  = lane >> 2;
    const int tig  = lane & 3;

    const int bx = (int)gridDim.x - 1 - (int)blockIdx.x;   // heavy tiles first
    const int h  = blockIdx.y;
    const int m0 = bx * 128;
    const int w16 = warp * 16;

    const float* Qh = Q + (size_t)h * S_LEN * DHEAD;
    const float* Kh = K + (size_t)h * S_LEN * DHEAD;
    const float* Vh = V + (size_t)h * S_LEN * DHEAD;

    // copy mapping for 64x64 tiles: 1024 chunks each
    const int cr  = tid >> 2;          // row 0..63
    const int ccc = (tid & 3) << 2;    // col 0,4,8,12  (16 cols -> 4 iters)

    auto issue_kv = [&](int jt, int st) {
        float* Ks = Kst + st * FL_KV_STAGE;
        float* Vs = Vst + st * FL_KV_STAGE;
        const int j0 = jt * 64;
#pragma unroll
        for (int i = 0; i < 4; ++i) {
            const int c = ccc + i * 16;
            cp_async16(Ks + cr * FSTR + c, Kh + (size_t)(j0 + cr) * DHEAD + c);
            cp_async16(Vs + cr * FSTR + c, Vh + (size_t)(j0 + cr) * DHEAD + c);
        }
        cp_commit();
    };

    issue_kv(0, 0);

    // ---- Q fragments, register resident (converted once) ----
    unsigned qa[8][4];
    {
        const int r0 = m0 + w16 + gid;
#pragma unroll
        for (int kk = 0; kk < 8; ++kk) {
            const int c = kk * 8 + tig;
            qa[kk][0] = f2tf32(Qh[(size_t)r0 * DHEAD + c]);
            qa[kk][1] = f2tf32(Qh[(size_t)(r0 + 8) * DHEAD + c]);
            qa[kk][2] = f2tf32(Qh[(size_t)r0 * DHEAD + c + 4]);
            qa[kk][3] = f2tf32(Qh[(size_t)(r0 + 8) * DHEAD + c + 4]);
        }
    }

    float o[8][4];
#pragma unroll
    for (int ni = 0; ni < 8; ++ni)
#pragma unroll
        for (int f = 0; f < 4; ++f) o[ni][f] = 0.f;
    float mrun0 = -1e30f, mrun1 = -1e30f;
    float lrun0 = 0.f,    lrun1 = 0.f;

    const float SCL = 0.125f * 1.44269504f;   // 1/8 * log2(e)

    const int nT = 2 * (bx + 1);
    for (int jt = 0; jt < nT; ++jt) {
        const int buf = jt & 1;
        if (jt + 1 < nT) { issue_kv(jt + 1, buf ^ 1); cp_wait<1>(); }
        else             { cp_wait<0>(); }
        __syncthreads();

        const float* Ks = Kst + buf * FL_KV_STAGE;
        const float* Vs = Vst + buf * FL_KV_STAGE;
        const int j0 = jt * 64;
        const bool masked = (jt >= 2 * bx);

        // ---- S = Q K^T ----
        float s[8][4];
#pragma unroll
        for (int ni = 0; ni < 8; ++ni)
#pragma unroll
            for (int f = 0; f < 4; ++f) s[ni][f] = 0.f;

#pragma unroll
        for (int kk = 0; kk < 8; ++kk) {
            const int k8 = kk * 8;
#pragma unroll
            for (int ni = 0; ni < 8; ++ni) {
                const int n = ni * 8 + gid;
                unsigned b0 = f2tf32(Ks[n * FSTR + k8 + tig]);
                unsigned b1 = f2tf32(Ks[n * FSTR + k8 + tig + 4]);
                mma_tf32(s[ni], qa[kk][0], qa[kk][1], qa[kk][2], qa[kk][3], b0, b1);
            }
        }

        // ---- scale (base-2) + causal mask ----
        if (masked) {
            const int q0 = m0 + w16 + gid;
            const int q1 = q0 + 8;
#pragma unroll
            for (int ni = 0; ni < 8; ++ni) {
                const int kc0 = j0 + ni * 8 + 2 * tig;
                const int kc1 = kc0 + 1;
                s[ni][0] = (kc0 <= q0) ? s[ni][0] * SCL : -1e30f;
                s[ni][1] = (kc1 <= q0) ? s[ni][1] * SCL : -1e30f;
                s[ni][2] = (kc0 <= q1) ? s[ni][2] * SCL : -1e30f;
                s[ni][3] = (kc1 <= q1) ? s[ni][3] * SCL : -1e30f;
            }
        } else {
#pragma unroll
            for (int ni = 0; ni < 8; ++ni)
#pragma unroll
                for (int f = 0; f < 4; ++f) s[ni][f] *= SCL;
        }

        // ---- online softmax (base-2), rows (w16+gid) and (+8) ----
        float mx0 = -1e30f, mx1 = -1e30f;
#pragma unroll
        for (int ni = 0; ni < 8; ++ni) {
            mx0 = fmaxf(mx0, fmaxf(s[ni][0], s[ni][1]));
            mx1 = fmaxf(mx1, fmaxf(s[ni][2], s[ni][3]));
        }
#pragma unroll
        for (int off = 1; off <= 2; off <<= 1) {
            mx0 = fmaxf(mx0, __shfl_xor_sync(0xffffffffu, mx0, off));
            mx1 = fmaxf(mx1, __shfl_xor_sync(0xffffffffu, mx1, off));
        }
        const float mnew0 = fmaxf(mrun0, mx0);
        const float mnew1 = fmaxf(mrun1, mx1);
        const float al0 = exp2f(mrun0 - mnew0);
        const float al1 = exp2f(mrun1 - mnew1);
        mrun0 = mnew0; mrun1 = mnew1;

        float ls0 = 0.f, ls1 = 0.f;
        const int r0 = w16 + gid;
#pragma unroll
        for (int ni = 0; ni < 8; ++ni) {
            const float p0 = exp2f(s[ni][0] - mnew0);
            const float p1 = exp2f(s[ni][1] - mnew0);
            const float p2 = exp2f(s[ni][2] - mnew1);
            const float p3 = exp2f(s[ni][3] - mnew1);
            ls0 += p0 + p1; ls1 += p2 + p3;
            const int c = ni * 8 + 2 * tig;
            Ps[r0 * FSTR + c]           = f2tf32(p0);
            Ps[r0 * FSTR + c + 1]       = f2tf32(p1);
            Ps[(r0 + 8) * FSTR + c]     = f2tf32(p2);
            Ps[(r0 + 8) * FSTR + c + 1] = f2tf32(p3);
        }
#pragma unroll
        for (int off = 1; off <= 2; off <<= 1) {
            ls0 += __shfl_xor_sync(0xffffffffu, ls0, off);
            ls1 += __shfl_xor_sync(0xffffffffu, ls1, off);
        }
        lrun0 = lrun0 * al0 + ls0;
        lrun1 = lrun1 * al1 + ls1;

#pragma unroll
        for (int ni = 0; ni < 8; ++ni) {
            o[ni][0] *= al0; o[ni][1] *= al0;
            o[ni][2] *= al1; o[ni][3] *= al1;
        }

        __syncwarp();   // Ps is warp-private

        // ---- O += P V ----
#pragma unroll
        for (int kk = 0; kk < 8; ++kk) {
            const int k8 = kk * 8;
            unsigned a0 = Ps[r0 * FSTR + k8 + tig];
            unsigned a1 = Ps[(r0 + 8) * FSTR + k8 + tig];
            unsigned a2 = Ps[r0 * FSTR + k8 + tig + 4];
            unsigned a3 = Ps[(r0 + 8) * FSTR + k8 + tig + 4];
#pragma unroll
            for (int ni = 0; ni < 8; ++ni) {
                const int n = ni * 8 + gid;
                unsigned b0 = f2tf32(Vs[(k8 + tig) * FSTR + n]);
                unsigned b1 = f2tf32(Vs[(k8 + tig + 4) * FSTR + n]);
                mma_tf32(o[ni], a0, a1, a2, a3, b0, b1);
            }
        }
        __syncthreads();   // done with this K/V stage before it is refilled
    }

    // epilogue: normalize + write [s][h*64 + d]
    const float inv0 = 1.f / lrun0;
    const float inv1 = 1.f / lrun1;
    const int rr = m0 + w16 + gid;
#pragma unroll
    for (int ni = 0; ni < 8; ++ni) {
        const int c = h * DHEAD + ni * 8 + 2 * tig;
        float* d0 = O + (size_t)rr * DMODEL + c;
        float* d1 = O + (size_t)(rr + 8) * DMODEL + c;
        d0[0] = o[ni][0] * inv0; d0[1] = o[ni][1] * inv0;
        d1[0] = o[ni][2] * inv1; d1[1] = o[ni][3] * inv1;
    }
}

// =================================================================
extern "C" void kernel_launch(void* const* d_in, const int* in_sizes, int n_in,
                              void* d_out, int out_size)
{
    const float* q  = (const float*)d_in[0];
    const float* k  = (const float*)d_in[1];
    const float* v  = (const float*)d_in[2];
    const float* wq = (const float*)d_in[3];
    const float* bq = (const float*)d_in[4];
    const float* wk = (const float*)d_in[5];
    const float* bk = (const float*)d_in[6];
    const float* wv = (const float*)d_in[7];
    const float* bv = (const float*)d_in[8];
    const float* wo = (const float*)d_in[9];
    const float* bo = (const float*)d_in[10];
    float* out = (float*)d_out;

    void *pq, *pk, *pv, *patt;
    cudaGetSymbolAddress(&pq,   g_qh);
    cudaGetSymbolAddress(&pk,   g_kh);
    cudaGetSymbolAddress(&pv,   g_vh);
    cudaGetSymbolAddress(&patt, g_att);
    float* gq   = (float*)pq;
    float* gk   = (float*)pk;
    float* gv   = (float*)pv;
    float* gatt = (float*)patt;

    static bool attr_done = false;
    if (!attr_done) {
        cudaFuncSetAttribute(gemm_tf32_kernel<true>,
                             cudaFuncAttributeMaxDynamicSharedMemorySize, GEMM_SMEM);
        cudaFuncSetAttribute(gemm_tf32_kernel<false>,
                             cudaFuncAttributeMaxDynamicSharedMemorySize, GEMM_SMEM);
        cudaFuncSetAttribute(flash_tf32_kernel,
                             cudaFuncAttributeMaxDynamicSharedMemorySize, FLASH_SMEM);
        attr_done = true;
    }

    // fused Q/K/V projections (blockIdx.z selects tuple)
    GemmArgs3 qkv;
    qkv.p[0] = { q, wq, bq, gq };
    qkv.p[1] = { k, wk, bk, gk };
    qkv.p[2] = { v, wv, bv, gv };
    gemm_tf32_kernel<true><<<dim3(DMODEL / 128, S_LEN / 128, 3), 256, GEMM_SMEM>>>(qkv);

    flash_tf32_kernel<<<dim3(S_LEN / 128, NHEADS), 256, FLASH_SMEM>>>(gq, gk, gv, gatt);

    GemmArgs3 oproj;
    oproj.p[0] = { gatt, wo, bo, out };
    oproj.p[1] = oproj.p[0];
    oproj.p[2] = oproj.p[0];
    gemm_tf32_kernel<false><<<dim3(DMODEL / 128, S_LEN / 128, 1), 256, GEMM_SMEM>>>(oproj);
}